// round 6
// baseline (speedup 1.0000x reference)
#include <cuda_runtime.h>
#include <cstdint>

// ---------------- problem constants (fixed by the dataset) ----------------
#define NMAX   60000
#define VMAX   50000
#define SEQL   30
#define HD     100      // hidden / feature dim
#define G3     300      // 3 * HD
#define NSM    152      // GB300 SM count

// ---------------- device scratch (static: no runtime allocation) ----------
// g_embW PLAIN layout: embW[v*300 + c] = emb[v].W_ih[c] + b_ih[c], c = g*100+j
__device__ float g_embW[VMAX * G3];
__device__ float g_hn  [NMAX * HD];     // GRU final hidden
__device__ float g_xw  [NMAX * HD];     // x @ W (reused for both convs)
__device__ float g_xc1 [NMAX * HD];     // conv1 output (pre-relu)
__device__ float g_xc2 [NMAX * HD];     // conv2 output (pre-relu)
__device__ float g_x   [NMAX * 2*HD];   // relu(concat(xc1, root1))
__device__ float g_dinv[NMAX];
__device__ int   g_deg [NMAX];

// ---------------- small helpers ----------------
typedef unsigned long long u64;

__device__ __forceinline__ u64 pack2(float lo, float hi) {
    u64 r; asm("mov.b64 %0, {%1, %2};" : "=l"(r) : "f"(lo), "f"(hi)); return r;
}
__device__ __forceinline__ void unpack2(u64 v, float &lo, float &hi) {
    asm("mov.b64 {%0, %1}, %2;" : "=f"(lo), "=f"(hi) : "l"(v));
}
__device__ __forceinline__ u64 fma2(u64 a, u64 b, u64 c) {
    u64 d; asm("fma.rn.f32x2 %0, %1, %2, %3;" : "=l"(d) : "l"(a), "l"(b), "l"(c)); return d;
}
__device__ __forceinline__ float sigmf(float x) {
    return __fdividef(1.f, 1.f + __expf(-x));
}
__device__ __forceinline__ float tanh_f(float x) {
    return fmaf(2.f, __fdividef(1.f, 1.f + __expf(-2.f * x)), -1.f);
}

// ================= degree / normalization =================
__global__ void k_deg_init(int N) {
    int i = blockIdx.x * blockDim.x + threadIdx.x;
    if (i < N) g_deg[i] = 1;             // self-loop
}
__global__ void k_deg_edges(const int* __restrict__ ei, int E) {
    int e = blockIdx.x * blockDim.x + threadIdx.x;
    if (e < E) atomicAdd(&g_deg[ei[E + e]], 1);   // dst = second row
}
__global__ void k_dinv(int N) {
    int i = blockIdx.x * blockDim.x + threadIdx.x;
    if (i < N) g_dinv[i] = rsqrtf((float)g_deg[i]);
}

// ================= kernel: embW (persistent tiled GEMM, plain layout) ======
// thread (n = tid&63, jc = tid>>6) computes cols [jc*60, jc*60+60) for vocab
// row base+n. sW[k*300+c] = W_ih[c*100+k].
#define EMBW_SMEM ((30000 + 6400) * 4)

__global__ __launch_bounds__(320, 1)
void k_embW(const float* __restrict__ emb, const float* __restrict__ W_ih,
            const float* __restrict__ b_ih, int V, int ntiles)
{
    extern __shared__ float sm[];
    float* sW = sm;           // [100][300]  sW[k*300+c] = W_ih[c][k]
    float* se = sm + 30000;   // [100][64]

    const int tid = threadIdx.x;
    const int n   = tid & 63;
    const int jc  = tid >> 6;

    for (int idx = tid; idx < G3 * HD; idx += 320) {
        int c = idx / HD, k = idx - c * HD;
        sW[k * G3 + c] = W_ih[idx];
    }

    for (int tile = blockIdx.x; tile < ntiles; tile += gridDim.x) {
        const int base = tile * 64;
        __syncthreads();   // protect se from previous iteration readers
        for (int idx = tid; idx < 64 * HD; idx += 320) {
            int nn = idx / HD, k = idx - nn * HD;
            int vg = min(base + nn, V - 1);
            se[k * 64 + nn] = emb[vg * HD + k];
        }
        __syncthreads();

        u64 acc[30];
        #pragma unroll
        for (int p = 0; p < 30; p++) acc[p] = 0ull;

        const float* wr0 = sW + jc * 60;
        #pragma unroll 2
        for (int k = 0; k < HD; k++) {
            float xv = se[k * 64 + n];
            u64 x2 = pack2(xv, xv);
            const float* wr = wr0 + k * G3;
            #pragma unroll
            for (int p = 0; p < 30; p++) {
                u64 wv = *(const u64*)(wr + p * 2);
                acc[p] = fma2(wv, x2, acc[p]);
            }
        }

        int v = base + n;
        if (v < V) {
            float* outp = g_embW + (long long)v * G3 + jc * 60;
            const float* bp = b_ih + jc * 60;
            #pragma unroll
            for (int p = 0; p < 30; p++) {
                float lo, hi; unpack2(acc[p], lo, hi);
                float2 o; o.x = lo + bp[p*2]; o.y = hi + bp[p*2 + 1];
                *(float2*)(outp + p*2) = o;
            }
        }
    }
}

// ================= fused persistent GRU (warp-owns-8-nodes) =================
// 384 threads = 12 warps. Each warp independently processes groups of 8 nodes.
// Lane l owns j-columns {2l,2l+1} (set0) and {2l+64,2l+65} (set1, valid l<18)
// of ALL 3 gates. W reads are coalesced LDS.64; h reads are cheap broadcasts.
// sh is warp-private -> NO block barriers in the recurrence.
#define GRU_TPB   384
#define GRU_WARPS 12
#define GRU_SMEM  ((30000 + 300 + GRU_WARPS*800) * 4 + GRU_WARPS*240*4)  // 171120 B

__global__ __launch_bounds__(GRU_TPB, 1)
void k_gru(const float* __restrict__ h0, const int* __restrict__ feat,
           const float* __restrict__ W_hh, const float* __restrict__ b_hh,
           int n_nodes, int n_groups)
{
    extern __shared__ float sm[];
    float* sWt  = sm;              // [100][300]  sWt[k*300+j] = W_hh[j][k]
    float* sb   = sm + 30000;      // [300]
    float* shb  = sm + 30300;      // [12][8][100]  per-warp h
    int*   stkb = (int*)(sm + 30300 + GRU_WARPS*800);  // [12][8][30]

    const int tid  = threadIdx.x;
    const int wid  = tid >> 5;
    const int lane = tid & 31;

    for (int idx = tid; idx < G3 * HD; idx += GRU_TPB) {
        int j = idx / HD, k = idx - j * HD;
        sWt[k * G3 + j] = W_hh[idx];
    }
    for (int idx = tid; idx < G3; idx += GRU_TPB) sb[idx] = b_hh[idx];
    __syncthreads();

    float* sh   = shb + wid * 800;      // sh[n*100 + k]
    int*   stok = stkb + wid * 240;     // stok[n*30 + t]

    const int  c0 = 2 * lane;                 // cols c0, c0+1 (always valid)
    const bool v1 = (2 * lane + 65) < HD;     // lane <= 17
    const int  c1 = v1 ? (2 * lane + 64) : 96;

    for (int g = blockIdx.x * GRU_WARPS + wid; g < n_groups;
         g += gridDim.x * GRU_WARPS) {
        const int base = g * 8;

        for (int idx = lane; idx < 800; idx += 32) {
            int n = idx / 100, k = idx - n * 100;
            int ng = min(base + n, n_nodes - 1);
            sh[idx] = h0[ng * HD + k];
        }
        for (int idx = lane; idx < 240; idx += 32) {
            int n = idx / 30, t = idx - n * 30;
            int ng = min(base + n, n_nodes - 1);
            stok[idx] = feat[ng * SEQL + t];
        }
        __syncwarp();

        for (int step = 0; step < SEQL; step++) {
            // ---- GEMM: 48 f32x2 accumulators (6 col-pairs x 8 nodes) ----
            u64 a0r[8], a0z[8], a0n[8], a1r[8], a1z[8], a1n[8];
            #pragma unroll
            for (int n = 0; n < 8; n++) {
                a0r[n] = a0z[n] = a0n[n] = 0ull;
                a1r[n] = a1z[n] = a1n[n] = 0ull;
            }

            #pragma unroll 2
            for (int k = 0; k < HD; k++) {
                const float* wk = sWt + k * G3;
                u64 w0r = *(const u64*)(wk + c0);
                u64 w0z = *(const u64*)(wk + 100 + c0);
                u64 w0n = *(const u64*)(wk + 200 + c0);
                u64 w1r = *(const u64*)(wk + c1);
                u64 w1z = *(const u64*)(wk + 100 + c1);
                u64 w1n = *(const u64*)(wk + 200 + c1);
                #pragma unroll
                for (int n = 0; n < 8; n++) {
                    float hv = sh[n * 100 + k];       // broadcast (1 wavefront)
                    u64 h2 = pack2(hv, hv);
                    a0r[n] = fma2(w0r, h2, a0r[n]);
                    a0z[n] = fma2(w0z, h2, a0z[n]);
                    a0n[n] = fma2(w0n, h2, a0n[n]);
                    a1r[n] = fma2(w1r, h2, a1r[n]);
                    a1z[n] = fma2(w1z, h2, a1z[n]);
                    a1n[n] = fma2(w1n, h2, a1n[n]);
                }
            }
            __syncwarp();   // all lanes done reading sh before gate writes

            // ---- gate phase (thread-local, exact math) ----
            float2 br0 = *(const float2*)(sb + c0);
            float2 bz0 = *(const float2*)(sb + 100 + c0);
            float2 bn0 = *(const float2*)(sb + 200 + c0);
            float2 br1 = *(const float2*)(sb + c1);
            float2 bz1 = *(const float2*)(sb + 100 + c1);
            float2 bn1 = *(const float2*)(sb + 200 + c1);

            #pragma unroll
            for (int n = 0; n < 8; n++) {
                int tok = stok[n * 30 + step];
                const float* ew = g_embW + (long long)tok * G3;
                {   // set 0
                    float2 er = *(const float2*)(ew + c0);
                    float2 ez = *(const float2*)(ew + 100 + c0);
                    float2 en = *(const float2*)(ew + 200 + c0);
                    float2 ho = *(const float2*)(sh + n * 100 + c0);
                    float gr0, gr1, gz0, gz1, gn0, gn1;
                    unpack2(a0r[n], gr0, gr1);
                    unpack2(a0z[n], gz0, gz1);
                    unpack2(a0n[n], gn0, gn1);
                    float r0 = sigmf(er.x + gr0 + br0.x);
                    float r1 = sigmf(er.y + gr1 + br0.y);
                    float z0 = sigmf(ez.x + gz0 + bz0.x);
                    float z1 = sigmf(ez.y + gz1 + bz0.y);
                    float nn0 = tanh_f(en.x + r0 * (gn0 + bn0.x));
                    float nn1 = tanh_f(en.y + r1 * (gn1 + bn0.y));
                    float2 o;
                    o.x = nn0 + z0 * (ho.x - nn0);
                    o.y = nn1 + z1 * (ho.y - nn1);
                    *(float2*)(sh + n * 100 + c0) = o;
                }
                if (v1) {   // set 1
                    float2 er = *(const float2*)(ew + c1);
                    float2 ez = *(const float2*)(ew + 100 + c1);
                    float2 en = *(const float2*)(ew + 200 + c1);
                    float2 ho = *(const float2*)(sh + n * 100 + c1);
                    float gr0, gr1, gz0, gz1, gn0, gn1;
                    unpack2(a1r[n], gr0, gr1);
                    unpack2(a1z[n], gz0, gz1);
                    unpack2(a1n[n], gn0, gn1);
                    float r0 = sigmf(er.x + gr0 + br1.x);
                    float r1 = sigmf(er.y + gr1 + br1.y);
                    float z0 = sigmf(ez.x + gz0 + bz1.x);
                    float z1 = sigmf(ez.y + gz1 + bz1.y);
                    float nn0 = tanh_f(en.x + r0 * (gn0 + bn1.x));
                    float nn1 = tanh_f(en.y + r1 * (gn1 + bn1.y));
                    float2 o;
                    o.x = nn0 + z0 * (ho.x - nn0);
                    o.y = nn1 + z1 * (ho.y - nn1);
                    *(float2*)(sh + n * 100 + c1) = o;
                }
            }
            __syncwarp();   // writes visible before next step's GEMM reads
        }

        // ---- store hn ----
        for (int idx = lane; idx < 800; idx += 32) {
            int n = idx / 100;
            int ng = base + n;
            if (ng < n_nodes) g_hn[ng * HD + (idx - n * 100)] = sh[idx];
        }
        __syncwarp();   // done with sh before next group overwrites it
    }
}

// ================= generic small GEMM: out[N,100] = x[N,K] @ W[K,100] ======
template<int K>
__device__ __forceinline__ void gemm_body(const float* __restrict__ x,
                                          const float* __restrict__ W,
                                          float* __restrict__ outp, int N)
{
    extern __shared__ float sg[];
    float* sxT = sg;            // [K][64]
    float* sW  = sg + K * 64;   // [K][100]
    const int tid  = threadIdx.x;
    const int base = blockIdx.x * 64;
    for (int idx = tid; idx < K * 64; idx += 256) {
        int nn = idx / K, k = idx - nn * K;
        int ng = min(base + nn, N - 1);
        sxT[k * 64 + nn] = x[ng * K + k];
    }
    for (int idx = tid; idx < K * 100; idx += 256) sW[idx] = W[idx];
    __syncthreads();

    const int n = tid & 63;
    const int q = tid >> 6;          // 0..3 -> 25 outputs each
    float acc[25];
    #pragma unroll
    for (int j = 0; j < 25; j++) acc[j] = 0.f;
    #pragma unroll 4
    for (int k = 0; k < K; k++) {
        float xk = sxT[k * 64 + n];
        const float* wr = sW + k * 100 + q * 25;
        #pragma unroll
        for (int j = 0; j < 25; j++) acc[j] = fmaf(xk, wr[j], acc[j]);
    }
    int ng = base + n;
    if (ng < N) {
        float* o = outp + ng * 100 + q * 25;
        #pragma unroll
        for (int j = 0; j < 25; j++) o[j] = acc[j];
    }
}

__global__ __launch_bounds__(256) void k_gemm1(const float* __restrict__ W1, int N) {
    gemm_body<100>(g_hn, W1, g_xw, N);
}
__global__ __launch_bounds__(256) void k_gemm2(const float* __restrict__ W2, int N) {
    gemm_body<200>(g_x, W2, g_xw, N);
}

// ================= GCN self-term init + edge aggregation ===================
__device__ __forceinline__ void init_self(const float* __restrict__ b,
                                          float* __restrict__ outp, int N)
{
    int gid = blockIdx.x * blockDim.x + threadIdx.x;
    if (gid >= N * HD) return;
    int n = gid / HD, j = gid - n * HD;
    float di = g_dinv[n];
    outp[gid] = fmaf(g_xw[gid], di * di, b[j]);
}
__global__ void k_init1(const float* __restrict__ b1, int N) { init_self(b1, g_xc1, N); }
__global__ void k_init2(const float* __restrict__ b2, int N) { init_self(b2, g_xc2, N); }

__device__ __forceinline__ void edge_body(float* __restrict__ outp,
                                          const int* __restrict__ ei, int E)
{
    int gid = blockIdx.x * blockDim.x + threadIdx.x;
    if (gid >= E * 25) return;
    int e = gid / 25;
    int c = gid - e * 25;
    int src = ei[e];
    int dst = ei[E + e];
    float coef = g_dinv[src] * g_dinv[dst];
    float4 v = *(const float4*)(g_xw + src * HD + c * 4);
    float* o = outp + dst * HD + c * 4;
    atomicAdd(o + 0, v.x * coef);
    atomicAdd(o + 1, v.y * coef);
    atomicAdd(o + 2, v.z * coef);
    atomicAdd(o + 3, v.w * coef);
}
__global__ void k_edge1(const int* __restrict__ ei, int E) { edge_body(g_xc1, ei, E); }
__global__ void k_edge2(const int* __restrict__ ei, int E) { edge_body(g_xc2, ei, E); }

// ================= concat/relu glue =================
__global__ void k_build_x(const int* __restrict__ indices, int N) {
    int gid = blockIdx.x * blockDim.x + threadIdx.x;
    if (gid >= N * 2 * HD) return;
    int n = gid / (2 * HD), j = gid - n * 2 * HD;
    float v = (j < HD) ? g_xc1[n * HD + j]
                       : g_hn[indices[n] * HD + (j - HD)];
    g_x[gid] = fmaxf(v, 0.f);
}
__global__ void k_final(const int* __restrict__ indices, float* __restrict__ out, int N) {
    int gid = blockIdx.x * blockDim.x + threadIdx.x;
    if (gid >= N * 2 * HD) return;
    int n = gid / (2 * HD), j = gid - n * 2 * HD;
    float v = (j < HD) ? fmaxf(g_xc2[n * HD + j], 0.f)
                       : g_xc1[indices[n] * HD + (j - HD)];   // root2 pre-relu
    out[gid] = v;
}

// ================= launch =================
extern "C" void kernel_launch(void* const* d_in, const int* in_sizes, int n_in,
                              void* d_out, int out_size)
{
    const int*   feat    = (const int*)  d_in[0];
    const int*   ei      = (const int*)  d_in[1];
    const int*   indices = (const int*)  d_in[2];
    const float* h0      = (const float*)d_in[3];
    const float* emb     = (const float*)d_in[4];
    const float* W_ih    = (const float*)d_in[5];
    const float* W_hh    = (const float*)d_in[6];
    const float* b_ih    = (const float*)d_in[7];
    const float* b_hh    = (const float*)d_in[8];
    const float* W1      = (const float*)d_in[9];
    const float* b1      = (const float*)d_in[10];
    const float* W2      = (const float*)d_in[11];
    const float* b2      = (const float*)d_in[12];
    float* out = (float*)d_out;

    const int N = in_sizes[0] / SEQL;     // 60000
    const int E = in_sizes[1] / 2;        // 120000
    const int V = in_sizes[4] / HD;       // 50000
    const int n_groups   = (N + 7) / 8;   // 8 nodes per warp-group
    const int embw_tiles = (V + 63) / 64;

    cudaFuncSetAttribute(k_gru,   cudaFuncAttributeMaxDynamicSharedMemorySize, GRU_SMEM);
    cudaFuncSetAttribute(k_embW,  cudaFuncAttributeMaxDynamicSharedMemorySize, EMBW_SMEM);
    cudaFuncSetAttribute(k_gemm1, cudaFuncAttributeMaxDynamicSharedMemorySize, (100*64 + 100*100) * 4);
    cudaFuncSetAttribute(k_gemm2, cudaFuncAttributeMaxDynamicSharedMemorySize, (200*64 + 200*100) * 4);

    // launch order chosen so k_gru is launch index 3 (ncu capture slot)
    k_deg_init <<<(N + 255) / 256, 256>>>(N);                               // 0
    k_deg_edges<<<(E + 255) / 256, 256>>>(ei, E);                           // 1
    k_embW<<<NSM, 320, EMBW_SMEM>>>(emb, W_ih, b_ih, V, embw_tiles);        // 2
    k_gru <<<NSM, GRU_TPB, GRU_SMEM>>>(h0, feat, W_hh, b_hh, N, n_groups);  // 3
    k_dinv     <<<(N + 255) / 256, 256>>>(N);                               // 4

    k_gemm1<<<(N + 63) / 64, 256, (100*64 + 100*100) * 4>>>(W1, N);         // 5
    k_init1<<<(N * HD + 255) / 256, 256>>>(b1, N);                          // 6
    k_edge1<<<(E * 25 + 255) / 256, 256>>>(ei, E);                          // 7

    k_build_x<<<(N * 2 * HD + 255) / 256, 256>>>(indices, N);               // 8

    k_gemm2<<<(N + 63) / 64, 256, (200*64 + 200*100) * 4>>>(W2, N);         // 9
    k_init2<<<(N * HD + 255) / 256, 256>>>(b2, N);                          // 10
    k_edge2<<<(E * 25 + 255) / 256, 256>>>(ei, E);                          // 11

    k_final<<<(N * 2 * HD + 255) / 256, 256>>>(indices, out, N);            // 12
}

// round 7
// speedup vs baseline: 1.0528x; 1.0528x over previous
#include <cuda_runtime.h>
#include <cstdint>

// ---------------- problem constants (fixed by the dataset) ----------------
#define NMAX   60000
#define VMAX   50000
#define SEQL   30
#define HD     100      // hidden / feature dim
#define G3     300      // 3 * HD
#define NSM    152      // GB300 SM count

// ---------------- device scratch (static: no runtime allocation) ----------
// g_embW PLAIN layout: embW[v*300 + c] = emb[v].W_ih[c] + b_ih[c], c = g*100+j
__device__ float g_embW[VMAX * G3];
__device__ float g_hn  [NMAX * HD];     // GRU final hidden
__device__ float g_xw  [NMAX * HD];     // x @ W (reused for both convs)
__device__ float g_xc1 [NMAX * HD];     // conv1 output (pre-relu)
__device__ float g_xc2 [NMAX * HD];     // conv2 output (pre-relu)
__device__ float g_x   [NMAX * 2*HD];   // relu(concat(xc1, root1))
__device__ float g_dinv[NMAX];
__device__ int   g_deg [NMAX];

// ---------------- small helpers ----------------
typedef unsigned long long u64;

__device__ __forceinline__ u64 pack2(float lo, float hi) {
    u64 r; asm("mov.b64 %0, {%1, %2};" : "=l"(r) : "f"(lo), "f"(hi)); return r;
}
__device__ __forceinline__ void unpack2(u64 v, float &lo, float &hi) {
    asm("mov.b64 {%0, %1}, %2;" : "=f"(lo), "=f"(hi) : "l"(v));
}
__device__ __forceinline__ u64 fma2(u64 a, u64 b, u64 c) {
    u64 d; asm("fma.rn.f32x2 %0, %1, %2, %3;" : "=l"(d) : "l"(a), "l"(b), "l"(c)); return d;
}
__device__ __forceinline__ float sigmf(float x) {
    return __fdividef(1.f, 1.f + __expf(-x));
}
__device__ __forceinline__ float tanh_f(float x) {
    return fmaf(2.f, __fdividef(1.f, 1.f + __expf(-2.f * x)), -1.f);
}

// ================= degree / normalization =================
__global__ void k_deg_init(int N) {
    int i = blockIdx.x * blockDim.x + threadIdx.x;
    if (i < N) g_deg[i] = 1;             // self-loop
}
__global__ void k_deg_edges(const int* __restrict__ ei, int E) {
    int e = blockIdx.x * blockDim.x + threadIdx.x;
    if (e < E) atomicAdd(&g_deg[ei[E + e]], 1);   // dst = second row
}
__global__ void k_dinv(int N) {
    int i = blockIdx.x * blockDim.x + threadIdx.x;
    if (i < N) g_dinv[i] = rsqrtf((float)g_deg[i]);
}

// ================= kernel: embW (persistent tiled GEMM, plain layout) ======
// thread (n = tid&63, jc = tid>>6) computes cols [jc*60, jc*60+60) for vocab
// row base+n. sW[k*300+c] = W_ih[c*100+k].
#define EMBW_SMEM ((30000 + 6400) * 4)

__global__ __launch_bounds__(320, 1)
void k_embW(const float* __restrict__ emb, const float* __restrict__ W_ih,
            const float* __restrict__ b_ih, int V, int ntiles)
{
    extern __shared__ float sm[];
    float* sW = sm;           // [100][300]  sW[k*300+c] = W_ih[c][k]
    float* se = sm + 30000;   // [100][64]

    const int tid = threadIdx.x;
    const int n   = tid & 63;
    const int jc  = tid >> 6;

    for (int idx = tid; idx < G3 * HD; idx += 320) {
        int c = idx / HD, k = idx - c * HD;
        sW[k * G3 + c] = W_ih[idx];
    }

    for (int tile = blockIdx.x; tile < ntiles; tile += gridDim.x) {
        const int base = tile * 64;
        __syncthreads();   // protect se from previous iteration readers
        for (int idx = tid; idx < 64 * HD; idx += 320) {
            int nn = idx / HD, k = idx - nn * HD;
            int vg = min(base + nn, V - 1);
            se[k * 64 + nn] = emb[vg * HD + k];
        }
        __syncthreads();

        u64 acc[30];
        #pragma unroll
        for (int p = 0; p < 30; p++) acc[p] = 0ull;

        const float* wr0 = sW + jc * 60;
        #pragma unroll 2
        for (int k = 0; k < HD; k++) {
            float xv = se[k * 64 + n];
            u64 x2 = pack2(xv, xv);
            const float* wr = wr0 + k * G3;
            #pragma unroll
            for (int p = 0; p < 30; p++) {
                u64 wv = *(const u64*)(wr + p * 2);
                acc[p] = fma2(wv, x2, acc[p]);
            }
        }

        int v = base + n;
        if (v < V) {
            float* outp = g_embW + (long long)v * G3 + jc * 60;
            const float* bp = b_ih + jc * 60;
            #pragma unroll
            for (int p = 0; p < 30; p++) {
                float lo, hi; unpack2(acc[p], lo, hi);
                float2 o; o.x = lo + bp[p*2]; o.y = hi + bp[p*2 + 1];
                *(float2*)(outp + p*2) = o;
            }
        }
    }
}

// ================= fused persistent GRU (warp-owns-8-nodes) =================
// 384 threads = 12 warps. Each warp independently processes groups of 8 nodes.
// Lane l owns j-columns {2l,2l+1} (set0) and {2l+64,2l+65} (set1, valid l<18)
// of ALL 3 gates. W reads are coalesced LDS.64; h reads are cheap broadcasts.
// sh is warp-private -> NO block barriers in the recurrence.
#define GRU_TPB   384
#define GRU_WARPS 12
#define GRU_SMEM  ((30000 + 300 + GRU_WARPS*800) * 4 + GRU_WARPS*240*4)  // 171120 B

__global__ __launch_bounds__(GRU_TPB, 1)
void k_gru(const float* __restrict__ h0, const int* __restrict__ feat,
           const float* __restrict__ W_hh, const float* __restrict__ b_hh,
           int n_nodes, int n_groups)
{
    extern __shared__ float sm[];
    float* sWt  = sm;              // [100][300]  sWt[k*300+j] = W_hh[j][k]
    float* sb   = sm + 30000;      // [300]
    float* shb  = sm + 30300;      // [12][8][100]  per-warp h
    int*   stkb = (int*)(sm + 30300 + GRU_WARPS*800);  // [12][8][30]

    const int tid  = threadIdx.x;
    const int wid  = tid >> 5;
    const int lane = tid & 31;

    for (int idx = tid; idx < G3 * HD; idx += GRU_TPB) {
        int j = idx / HD, k = idx - j * HD;
        sWt[k * G3 + j] = W_hh[idx];
    }
    for (int idx = tid; idx < G3; idx += GRU_TPB) sb[idx] = b_hh[idx];
    __syncthreads();

    float* sh   = shb + wid * 800;      // sh[n*100 + k]
    int*   stok = stkb + wid * 240;     // stok[n*30 + t]

    const int  c0 = 2 * lane;                 // cols c0, c0+1 (always valid)
    const bool v1 = (2 * lane + 65) < HD;     // lane <= 17
    const int  c1 = v1 ? (2 * lane + 64) : 96;

    for (int g = blockIdx.x * GRU_WARPS + wid; g < n_groups;
         g += gridDim.x * GRU_WARPS) {
        const int base = g * 8;

        for (int idx = lane; idx < 800; idx += 32) {
            int n = idx / 100, k = idx - n * 100;
            int ng = min(base + n, n_nodes - 1);
            sh[idx] = h0[ng * HD + k];
        }
        for (int idx = lane; idx < 240; idx += 32) {
            int n = idx / 30, t = idx - n * 30;
            int ng = min(base + n, n_nodes - 1);
            stok[idx] = feat[ng * SEQL + t];
        }
        __syncwarp();

        for (int step = 0; step < SEQL; step++) {
            // ---- GEMM: 48 f32x2 accumulators (6 col-pairs x 8 nodes) ----
            u64 a0r[8], a0z[8], a0n[8], a1r[8], a1z[8], a1n[8];
            #pragma unroll
            for (int n = 0; n < 8; n++) {
                a0r[n] = a0z[n] = a0n[n] = 0ull;
                a1r[n] = a1z[n] = a1n[n] = 0ull;
            }

            #pragma unroll 2
            for (int k = 0; k < HD; k++) {
                const float* wk = sWt + k * G3;
                u64 w0r = *(const u64*)(wk + c0);
                u64 w0z = *(const u64*)(wk + 100 + c0);
                u64 w0n = *(const u64*)(wk + 200 + c0);
                u64 w1r = *(const u64*)(wk + c1);
                u64 w1z = *(const u64*)(wk + 100 + c1);
                u64 w1n = *(const u64*)(wk + 200 + c1);
                #pragma unroll
                for (int n = 0; n < 8; n++) {
                    float hv = sh[n * 100 + k];       // broadcast (1 wavefront)
                    u64 h2 = pack2(hv, hv);
                    a0r[n] = fma2(w0r, h2, a0r[n]);
                    a0z[n] = fma2(w0z, h2, a0z[n]);
                    a0n[n] = fma2(w0n, h2, a0n[n]);
                    a1r[n] = fma2(w1r, h2, a1r[n]);
                    a1z[n] = fma2(w1z, h2, a1z[n]);
                    a1n[n] = fma2(w1n, h2, a1n[n]);
                }
            }
            __syncwarp();   // all lanes done reading sh before gate writes

            // ---- gate phase (thread-local, exact math) ----
            float2 br0 = *(const float2*)(sb + c0);
            float2 bz0 = *(const float2*)(sb + 100 + c0);
            float2 bn0 = *(const float2*)(sb + 200 + c0);
            float2 br1 = *(const float2*)(sb + c1);
            float2 bz1 = *(const float2*)(sb + 100 + c1);
            float2 bn1 = *(const float2*)(sb + 200 + c1);

            #pragma unroll
            for (int n = 0; n < 8; n++) {
                int tok = stok[n * 30 + step];
                const float* ew = g_embW + (long long)tok * G3;
                {   // set 0
                    float2 er = *(const float2*)(ew + c0);
                    float2 ez = *(const float2*)(ew + 100 + c0);
                    float2 en = *(const float2*)(ew + 200 + c0);
                    float2 ho = *(const float2*)(sh + n * 100 + c0);
                    float gr0, gr1, gz0, gz1, gn0, gn1;
                    unpack2(a0r[n], gr0, gr1);
                    unpack2(a0z[n], gz0, gz1);
                    unpack2(a0n[n], gn0, gn1);
                    float r0 = sigmf(er.x + gr0 + br0.x);
                    float r1 = sigmf(er.y + gr1 + br0.y);
                    float z0 = sigmf(ez.x + gz0 + bz0.x);
                    float z1 = sigmf(ez.y + gz1 + bz0.y);
                    float nn0 = tanh_f(en.x + r0 * (gn0 + bn0.x));
                    float nn1 = tanh_f(en.y + r1 * (gn1 + bn0.y));
                    float2 o;
                    o.x = nn0 + z0 * (ho.x - nn0);
                    o.y = nn1 + z1 * (ho.y - nn1);
                    *(float2*)(sh + n * 100 + c0) = o;
                }
                if (v1) {   // set 1
                    float2 er = *(const float2*)(ew + c1);
                    float2 ez = *(const float2*)(ew + 100 + c1);
                    float2 en = *(const float2*)(ew + 200 + c1);
                    float2 ho = *(const float2*)(sh + n * 100 + c1);
                    float gr0, gr1, gz0, gz1, gn0, gn1;
                    unpack2(a1r[n], gr0, gr1);
                    unpack2(a1z[n], gz0, gz1);
                    unpack2(a1n[n], gn0, gn1);
                    float r0 = sigmf(er.x + gr0 + br1.x);
                    float r1 = sigmf(er.y + gr1 + br1.y);
                    float z0 = sigmf(ez.x + gz0 + bz1.x);
                    float z1 = sigmf(ez.y + gz1 + bz1.y);
                    float nn0 = tanh_f(en.x + r0 * (gn0 + bn1.x));
                    float nn1 = tanh_f(en.y + r1 * (gn1 + bn1.y));
                    float2 o;
                    o.x = nn0 + z0 * (ho.x - nn0);
                    o.y = nn1 + z1 * (ho.y - nn1);
                    *(float2*)(sh + n * 100 + c1) = o;
                }
            }
            __syncwarp();   // writes visible before next step's GEMM reads
        }

        // ---- store hn ----
        for (int idx = lane; idx < 800; idx += 32) {
            int n = idx / 100;
            int ng = base + n;
            if (ng < n_nodes) g_hn[ng * HD + (idx - n * 100)] = sh[idx];
        }
        __syncwarp();   // done with sh before next group overwrites it
    }
}

// ================= generic small GEMM: out[N,100] = x[N,K] @ W[K,100] ======
template<int K>
__device__ __forceinline__ void gemm_body(const float* __restrict__ x,
                                          const float* __restrict__ W,
                                          float* __restrict__ outp, int N)
{
    extern __shared__ float sg[];
    float* sxT = sg;            // [K][64]
    float* sW  = sg + K * 64;   // [K][100]
    const int tid  = threadIdx.x;
    const int base = blockIdx.x * 64;
    for (int idx = tid; idx < K * 64; idx += 256) {
        int nn = idx / K, k = idx - nn * K;
        int ng = min(base + nn, N - 1);
        sxT[k * 64 + nn] = x[ng * K + k];
    }
    for (int idx = tid; idx < K * 100; idx += 256) sW[idx] = W[idx];
    __syncthreads();

    const int n = tid & 63;
    const int q = tid >> 6;          // 0..3 -> 25 outputs each
    float acc[25];
    #pragma unroll
    for (int j = 0; j < 25; j++) acc[j] = 0.f;
    #pragma unroll 4
    for (int k = 0; k < K; k++) {
        float xk = sxT[k * 64 + n];
        const float* wr = sW + k * 100 + q * 25;
        #pragma unroll
        for (int j = 0; j < 25; j++) acc[j] = fmaf(xk, wr[j], acc[j]);
    }
    int ng = base + n;
    if (ng < N) {
        float* o = outp + ng * 100 + q * 25;
        #pragma unroll
        for (int j = 0; j < 25; j++) o[j] = acc[j];
    }
}

__global__ __launch_bounds__(256) void k_gemm1(const float* __restrict__ W1, int N) {
    gemm_body<100>(g_hn, W1, g_xw, N);
}
__global__ __launch_bounds__(256) void k_gemm2(const float* __restrict__ W2, int N) {
    gemm_body<200>(g_x, W2, g_xw, N);
}

// ================= GCN self-term init + edge aggregation ===================
__device__ __forceinline__ void init_self(const float* __restrict__ b,
                                          float* __restrict__ outp, int N)
{
    int gid = blockIdx.x * blockDim.x + threadIdx.x;
    if (gid >= N * HD) return;
    int n = gid / HD, j = gid - n * HD;
    float di = g_dinv[n];
    outp[gid] = fmaf(g_xw[gid], di * di, b[j]);
}
__global__ void k_init1(const float* __restrict__ b1, int N) { init_self(b1, g_xc1, N); }
__global__ void k_init2(const float* __restrict__ b2, int N) { init_self(b2, g_xc2, N); }

__device__ __forceinline__ void edge_body(float* __restrict__ outp,
                                          const int* __restrict__ ei, int E)
{
    int gid = blockIdx.x * blockDim.x + threadIdx.x;
    if (gid >= E * 25) return;
    int e = gid / 25;
    int c = gid - e * 25;
    int src = ei[e];
    int dst = ei[E + e];
    float coef = g_dinv[src] * g_dinv[dst];
    float4 v = *(const float4*)(g_xw + src * HD + c * 4);
    float* o = outp + dst * HD + c * 4;
    atomicAdd(o + 0, v.x * coef);
    atomicAdd(o + 1, v.y * coef);
    atomicAdd(o + 2, v.z * coef);
    atomicAdd(o + 3, v.w * coef);
}
__global__ void k_edge1(const int* __restrict__ ei, int E) { edge_body(g_xc1, ei, E); }
__global__ void k_edge2(const int* __restrict__ ei, int E) { edge_body(g_xc2, ei, E); }

// ================= concat/relu glue =================
__global__ void k_build_x(const int* __restrict__ indices, int N) {
    int gid = blockIdx.x * blockDim.x + threadIdx.x;
    if (gid >= N * 2 * HD) return;
    int n = gid / (2 * HD), j = gid - n * 2 * HD;
    float v = (j < HD) ? g_xc1[n * HD + j]
                       : g_hn[indices[n] * HD + (j - HD)];
    g_x[gid] = fmaxf(v, 0.f);
}
__global__ void k_final(const int* __restrict__ indices, float* __restrict__ out, int N) {
    int gid = blockIdx.x * blockDim.x + threadIdx.x;
    if (gid >= N * 2 * HD) return;
    int n = gid / (2 * HD), j = gid - n * 2 * HD;
    float v = (j < HD) ? fmaxf(g_xc2[n * HD + j], 0.f)
                       : g_xc1[indices[n] * HD + (j - HD)];   // root2 pre-relu
    out[gid] = v;
}

// ================= launch =================
extern "C" void kernel_launch(void* const* d_in, const int* in_sizes, int n_in,
                              void* d_out, int out_size)
{
    const int*   feat    = (const int*)  d_in[0];
    const int*   ei      = (const int*)  d_in[1];
    const int*   indices = (const int*)  d_in[2];
    const float* h0      = (const float*)d_in[3];
    const float* emb     = (const float*)d_in[4];
    const float* W_ih    = (const float*)d_in[5];
    const float* W_hh    = (const float*)d_in[6];
    const float* b_ih    = (const float*)d_in[7];
    const float* b_hh    = (const float*)d_in[8];
    const float* W1      = (const float*)d_in[9];
    const float* b1      = (const float*)d_in[10];
    const float* W2      = (const float*)d_in[11];
    const float* b2      = (const float*)d_in[12];
    float* out = (float*)d_out;

    const int N = in_sizes[0] / SEQL;     // 60000
    const int E = in_sizes[1] / 2;        // 120000
    const int V = in_sizes[4] / HD;       // 50000
    const int n_groups   = (N + 7) / 8;   // 8 nodes per warp-group
    const int embw_tiles = (V + 63) / 64;

    cudaFuncSetAttribute(k_gru,   cudaFuncAttributeMaxDynamicSharedMemorySize, GRU_SMEM);
    cudaFuncSetAttribute(k_embW,  cudaFuncAttributeMaxDynamicSharedMemorySize, EMBW_SMEM);
    cudaFuncSetAttribute(k_gemm1, cudaFuncAttributeMaxDynamicSharedMemorySize, (100*64 + 100*100) * 4);
    cudaFuncSetAttribute(k_gemm2, cudaFuncAttributeMaxDynamicSharedMemorySize, (200*64 + 200*100) * 4);

    // launch order chosen so k_gru is launch index 3 (ncu capture slot)
    k_deg_init <<<(N + 255) / 256, 256>>>(N);                               // 0
    k_deg_edges<<<(E + 255) / 256, 256>>>(ei, E);                           // 1
    k_embW<<<NSM, 320, EMBW_SMEM>>>(emb, W_ih, b_ih, V, embw_tiles);        // 2
    k_gru <<<NSM, GRU_TPB, GRU_SMEM>>>(h0, feat, W_hh, b_hh, N, n_groups);  // 3
    k_dinv     <<<(N + 255) / 256, 256>>>(N);                               // 4

    k_gemm1<<<(N + 63) / 64, 256, (100*64 + 100*100) * 4>>>(W1, N);         // 5
    k_init1<<<(N * HD + 255) / 256, 256>>>(b1, N);                          // 6
    k_edge1<<<(E * 25 + 255) / 256, 256>>>(ei, E);                          // 7

    k_build_x<<<(N * 2 * HD + 255) / 256, 256>>>(indices, N);               // 8

    k_gemm2<<<(N + 63) / 64, 256, (200*64 + 200*100) * 4>>>(W2, N);         // 9
    k_init2<<<(N * HD + 255) / 256, 256>>>(b2, N);                          // 10
    k_edge2<<<(E * 25 + 255) / 256, 256>>>(ei, E);                          // 11

    k_final<<<(N * 2 * HD + 255) / 256, 256>>>(indices, out, N);            // 12
}

// round 9
// speedup vs baseline: 1.1816x; 1.1223x over previous
#include <cuda_runtime.h>
#include <cuda_bf16.h>
#include <cstdint>

#define NMAX   60000
#define VMAX   50000
#define SEQL   30
#define HD     100
#define G3     300
#define NSM    152

typedef unsigned long long u64;

__device__ float g_embW[VMAX * G3];
__device__ float g_hn  [NMAX * HD];
__device__ float g_xw  [NMAX * HD];
__device__ float g_xc1 [NMAX * HD];
__device__ float g_xc2 [NMAX * HD];
__device__ float g_x   [NMAX * 2*HD];
__device__ float g_dinv[NMAX];
__device__ int   g_deg [NMAX];

__device__ __forceinline__ u64 pack2(float lo, float hi) {
    u64 r; asm("mov.b64 %0, {%1, %2};" : "=l"(r) : "f"(lo), "f"(hi)); return r;
}
__device__ __forceinline__ void unpack2(u64 v, float &lo, float &hi) {
    asm("mov.b64 {%0, %1}, %2;" : "=f"(lo), "=f"(hi) : "l"(v));
}
__device__ __forceinline__ u64 fma2(u64 a, u64 b, u64 c) {
    u64 d; asm("fma.rn.f32x2 %0, %1, %2, %3;" : "=l"(d) : "l"(a), "l"(b), "l"(c)); return d;
}
__device__ __forceinline__ float sigmf(float x) { return __fdividef(1.f, 1.f + __expf(-x)); }
__device__ __forceinline__ float tanh_f(float x) {
    return fmaf(2.f, __fdividef(1.f, 1.f + __expf(-2.f * x)), -1.f);
}
__device__ __forceinline__ float bf16f(uint32_t b16) {
    uint32_t u = b16 << 16; float f; asm("mov.b32 %0, %1;" : "=f"(f) : "r"(u)); return f;
}
__device__ __forceinline__ uint32_t s2u(const void* p) {
    uint32_t a; asm("{ .reg .u64 t; cvta.to.shared.u64 t, %1; cvt.u32.u64 %0, t; }" : "=r"(a) : "l"(p));
    return a;
}

// ================= degree =================
__global__ void k_deg_init(int N) {
    int i = blockIdx.x * blockDim.x + threadIdx.x; if (i < N) g_deg[i] = 1;
}
__global__ void k_deg_edges(const int* __restrict__ ei, int E) {
    int e = blockIdx.x * blockDim.x + threadIdx.x; if (e < E) atomicAdd(&g_deg[ei[E + e]], 1);
}
__global__ void k_dinv(int N) {
    int i = blockIdx.x * blockDim.x + threadIdx.x; if (i < N) g_dinv[i] = rsqrtf((float)g_deg[i]);
}

// ================= embW table (fp32, proven) =================
#define EMBW_SMEM ((30000 + 6400) * 4)
__global__ __launch_bounds__(320, 1)
void k_embW(const float* __restrict__ emb, const float* __restrict__ W_ih,
            const float* __restrict__ b_ih, int V, int ntiles)
{
    extern __shared__ float sm[];
    float* sW = sm; float* se = sm + 30000;
    const int tid = threadIdx.x, n = tid & 63, jc = tid >> 6;
    for (int idx = tid; idx < G3 * HD; idx += 320) {
        int c = idx / HD, k = idx - c * HD;
        sW[k * G3 + c] = W_ih[idx];
    }
    for (int tile = blockIdx.x; tile < ntiles; tile += gridDim.x) {
        const int base = tile * 64;
        __syncthreads();
        for (int idx = tid; idx < 64 * HD; idx += 320) {
            int nn = idx / HD, k = idx - nn * HD;
            se[k * 64 + nn] = emb[min(base + nn, V - 1) * HD + k];
        }
        __syncthreads();
        u64 acc[30];
        #pragma unroll
        for (int p = 0; p < 30; p++) acc[p] = 0ull;
        const float* wr0 = sW + jc * 60;
        #pragma unroll 2
        for (int k = 0; k < HD; k++) {
            float xv = se[k * 64 + n];
            u64 x2 = pack2(xv, xv);
            const float* wr = wr0 + k * G3;
            #pragma unroll
            for (int p = 0; p < 30; p++) acc[p] = fma2(*(const u64*)(wr + p * 2), x2, acc[p]);
        }
        int v = base + n;
        if (v < V) {
            float* o = g_embW + (long long)v * G3 + jc * 60;
            const float* bp = b_ih + jc * 60;
            #pragma unroll
            for (int p = 0; p < 30; p++) {
                float lo, hi; unpack2(acc[p], lo, hi);
                float2 w; w.x = lo + bp[p*2]; w.y = hi + bp[p*2+1];
                *(float2*)(o + p*2) = w;
            }
        }
    }
}

// ================= HMMA GRU (mma.sync m16n8k16 bf16) =================
// SMEM layout (bytes):
//   FRAG: 14 ktd x 39 nt x 32 lanes x 8B  = 139776   (B fragments, precomputed)
//   A:    64 rows x 496B (248 bf16: 112 hi | 112 lo | 24 pad)  = 31744
//   TOK:  64 x 30 ints = 7680
//   BHH:  300 floats = 1200
#define FRAG_OFF 0
#define A_OFF    139776
#define A_STR    496
#define TOK_OFF  171520
#define BHH_OFF  179200
#define MMASMEM  180400

__global__ __launch_bounds__(256, 1)
void k_gru_mma(const float* __restrict__ h0, const int* __restrict__ feat,
               const float* __restrict__ W_hh, const float* __restrict__ b_hh,
               int n_nodes, int ntiles)
{
    extern __shared__ char smc[];
    const uint32_t sb = s2u(smc);
    const int tid = threadIdx.x, wid = tid >> 5, lane = tid & 31;
    const int m = wid & 3, nhalf = wid >> 2;
    const int g = lane >> 2, t = lane & 3;
    const int qlo = nhalf ? 7 : 0, qcnt = nhalf ? 6 : 7;
    float* sbhh = (float*)(smc + BHH_OFF);
    int*   stok = (int*)(smc + TOK_OFF);

    // ---- one-time: B fragments + biases ----
    for (int w = tid; w < 14 * 39 * 32; w += 256) {
        int lan = w & 31, tile = w >> 5;
        int nt = tile % 39, ktd = tile / 39;
        int gg = lan >> 2, tt = lan & 3;
        int gate = nt / 13, j = (nt % 13) * 8 + gg;
        bool isLo = (ktd >= 7);
        int k0 = (isLo ? ktd - 7 : ktd) * 16 + tt * 2;
        uint32_t br[2];
        #pragma unroll
        for (int r = 0; r < 2; r++) {
            uint32_t pk = 0;
            #pragma unroll
            for (int e = 0; e < 2; e++) {
                int kk = k0 + r * 8 + e;
                uint16_t bits = 0;
                if (j < 100 && kk < 100) {
                    float wv = W_hh[(gate * 100 + j) * 100 + kk];
                    __nv_bfloat16 hb = __float2bfloat16_rn(wv);
                    if (isLo) hb = __float2bfloat16_rn(wv - __bfloat162float(hb));
                    bits = __bfloat16_as_ushort(hb);
                }
                pk |= (uint32_t)bits << (16 * e);
            }
            br[r] = pk;
        }
        *(uint2*)(smc + FRAG_OFF + tile * 256 + lan * 8) = make_uint2(br[0], br[1]);
    }
    for (int i = tid; i < G3; i += 256) sbhh[i] = b_hh[i];
    __syncthreads();

    const int n0l = m * 16 + g, n1l = n0l + 8;

    for (int tile = blockIdx.x; tile < ntiles; tile += gridDim.x) {
        const int nbase = tile * 64;
        __syncthreads();   // previous tile fully consumed
        for (int i = tid; i < 64 * SEQL; i += 256) {
            int nl = i / SEQL, tt = i - nl * SEQL;
            stok[nl * SEQL + tt] = feat[(long long)min(nbase + nl, n_nodes - 1) * SEQL + tt];
        }
        for (int i = tid; i < 64 * 248; i += 256) {
            int row = i / 248, col = i - row * 248;
            uint16_t v = 0;
            if (col < 224) {
                int seg = col / 112, k = col - seg * 112;
                if (k < 100) {
                    float hv = h0[(long long)min(nbase + row, n_nodes - 1) * HD + k];
                    __nv_bfloat16 hb = __float2bfloat16_rn(hv);
                    if (seg == 1) hb = __float2bfloat16_rn(hv - __bfloat162float(hb));
                    v = __bfloat16_as_ushort(hb);
                }
            }
            *(uint16_t*)(smc + A_OFF + row * A_STR + col * 2) = v;
        }
        __syncthreads();

        for (int st = 0; st < SEQL; st++) {
            // ---- GEMM: gh = [h_hi|h_lo|h_hi] x [W_hi|W_hi|W_lo] ----
            float C[3][7][4];
            #pragma unroll
            for (int ga = 0; ga < 3; ga++)
                #pragma unroll
                for (int qi = 0; qi < 7; qi++)
                    #pragma unroll
                    for (int e = 0; e < 4; e++) C[ga][qi][e] = 0.f;

            const uint32_t abase = sb + A_OFF + (m * 16 + (lane & 15)) * A_STR + (lane >> 4) * 16;
            #pragma unroll
            for (int kt = 0; kt < 21; kt++) {
                int acol = (kt < 7) ? kt * 32 : (kt < 14) ? 224 + (kt - 7) * 32 : (kt - 14) * 32;
                int ktd  = (kt < 7) ? kt : kt - 7;
                uint32_t a0, a1, a2, a3;
                asm volatile("ldmatrix.sync.aligned.m8n8.x4.shared.b16 {%0,%1,%2,%3}, [%4];"
                    : "=r"(a0), "=r"(a1), "=r"(a2), "=r"(a3) : "r"(abase + acol));
                #pragma unroll
                for (int ga = 0; ga < 3; ga++) {
                    #pragma unroll
                    for (int qi = 0; qi < 7; qi++) {
                        if (qi < qcnt) {
                            int nt = ga * 13 + qlo + qi;
                            uint32_t b0, b1;
                            asm volatile("ld.shared.v2.b32 {%0,%1}, [%2];"
                                : "=r"(b0), "=r"(b1)
                                : "r"(sb + FRAG_OFF + (ktd * 39 + nt) * 256 + lane * 8));
                            asm volatile(
                                "mma.sync.aligned.m16n8k16.row.col.f32.bf16.bf16.f32 "
                                "{%0,%1,%2,%3}, {%4,%5,%6,%7}, {%8,%9}, {%0,%1,%2,%3};"
                                : "+f"(C[ga][qi][0]), "+f"(C[ga][qi][1]),
                                  "+f"(C[ga][qi][2]), "+f"(C[ga][qi][3])
                                : "r"(a0), "r"(a1), "r"(a2), "r"(a3), "r"(b0), "r"(b1));
                        }
                    }
                }
            }
            __syncthreads();   // all A reads done before h writes

            // ---- gate phase ----
            const bool last = (st == SEQL - 1);
            #pragma unroll
            for (int qi = 0; qi < 7; qi++) {
                if (qi < qcnt) {
                    int j = (qlo + qi) * 8 + 2 * t;
                    if (j < 100) {
                        float2 bhr = *(const float2*)(sbhh + j);
                        float2 bhz = *(const float2*)(sbhh + 100 + j);
                        float2 bhn = *(const float2*)(sbhh + 200 + j);
                        #pragma unroll
                        for (int nd = 0; nd < 2; nd++) {
                            int nl = nd ? n1l : n0l;
                            int gn = nbase + nl;
                            int tok = stok[nl * SEQL + st];
                            const float* ew = g_embW + (long long)tok * G3;
                            float2 xr = __ldg((const float2*)(ew + j));
                            float2 xz = __ldg((const float2*)(ew + 100 + j));
                            float2 xn = __ldg((const float2*)(ew + 200 + j));
                            char* hrow = smc + A_OFF + nl * A_STR;
                            uint32_t hhi = *(uint32_t*)(hrow + 2 * j);
                            uint32_t hlo = *(uint32_t*)(hrow + 224 + 2 * j);
                            float ho0 = bf16f(hhi & 0xffffu) + bf16f(hlo & 0xffffu);
                            float ho1 = bf16f(hhi >> 16) + bf16f(hlo >> 16);
                            float r0 = sigmf(xr.x + C[0][qi][2*nd]   + bhr.x);
                            float r1 = sigmf(xr.y + C[0][qi][2*nd+1] + bhr.y);
                            float z0 = sigmf(xz.x + C[1][qi][2*nd]   + bhz.x);
                            float z1 = sigmf(xz.y + C[1][qi][2*nd+1] + bhz.y);
                            float nv0 = tanh_f(xn.x + r0 * (C[2][qi][2*nd]   + bhn.x));
                            float nv1 = tanh_f(xn.y + r1 * (C[2][qi][2*nd+1] + bhn.y));
                            float h0n = nv0 + z0 * (ho0 - nv0);
                            float h1n = nv1 + z1 * (ho1 - nv1);
                            if (last) {
                                if (gn < n_nodes)
                                    *(float2*)(g_hn + (long long)gn * HD + j) = make_float2(h0n, h1n);
                            } else {
                                __nv_bfloat16 ah = __float2bfloat16_rn(h0n);
                                __nv_bfloat16 bh = __float2bfloat16_rn(h1n);
                                __nv_bfloat16 al = __float2bfloat16_rn(h0n - __bfloat162float(ah));
                                __nv_bfloat16 bl = __float2bfloat16_rn(h1n - __bfloat162float(bh));
                                *(uint32_t*)(hrow + 2 * j) =
                                    (uint32_t)__bfloat16_as_ushort(ah) |
                                    ((uint32_t)__bfloat16_as_ushort(bh) << 16);
                                *(uint32_t*)(hrow + 224 + 2 * j) =
                                    (uint32_t)__bfloat16_as_ushort(al) |
                                    ((uint32_t)__bfloat16_as_ushort(bl) << 16);
                            }
                        }
                    }
                }
            }
            __syncthreads();   // h writes visible before next step's GEMM
        }
    }
}

// ================= small GEMMs / GCN / glue (proven) =================
template<int K>
__device__ __forceinline__ void gemm_body(const float* __restrict__ x,
    const float* __restrict__ W, float* __restrict__ outp, int N)
{
    extern __shared__ float sg[];
    float* sxT = sg; float* sW = sg + K * 64;
    const int tid = threadIdx.x, base = blockIdx.x * 64;
    for (int idx = tid; idx < K * 64; idx += 256) {
        int nn = idx / K, k = idx - nn * K;
        sxT[k * 64 + nn] = x[min(base + nn, N - 1) * K + k];
    }
    for (int idx = tid; idx < K * 100; idx += 256) sW[idx] = W[idx];
    __syncthreads();
    const int n = tid & 63, q = tid >> 6;
    float acc[25];
    #pragma unroll
    for (int j = 0; j < 25; j++) acc[j] = 0.f;
    #pragma unroll 4
    for (int k = 0; k < K; k++) {
        float xk = sxT[k * 64 + n];
        const float* wr = sW + k * 100 + q * 25;
        #pragma unroll
        for (int j = 0; j < 25; j++) acc[j] = fmaf(xk, wr[j], acc[j]);
    }
    int ng = base + n;
    if (ng < N) {
        float* o = outp + ng * 100 + q * 25;
        #pragma unroll
        for (int j = 0; j < 25; j++) o[j] = acc[j];
    }
}
__global__ __launch_bounds__(256) void k_gemm1(const float* __restrict__ W1, int N) {
    gemm_body<100>(g_hn, W1, g_xw, N);
}
__global__ __launch_bounds__(256) void k_gemm2(const float* __restrict__ W2, int N) {
    gemm_body<200>(g_x, W2, g_xw, N);
}
__device__ __forceinline__ void init_self(const float* __restrict__ b, float* __restrict__ o, int N) {
    int gid = blockIdx.x * blockDim.x + threadIdx.x;
    if (gid >= N * HD) return;
    int n = gid / HD, j = gid - n * HD;
    float di = g_dinv[n];
    o[gid] = fmaf(g_xw[gid], di * di, b[j]);
}
__global__ void k_init1(const float* __restrict__ b1, int N) { init_self(b1, g_xc1, N); }
__global__ void k_init2(const float* __restrict__ b2, int N) { init_self(b2, g_xc2, N); }
__device__ __forceinline__ void edge_body(float* __restrict__ o, const int* __restrict__ ei, int E) {
    int gid = blockIdx.x * blockDim.x + threadIdx.x;
    if (gid >= E * 25) return;
    int e = gid / 25, c = gid - e * 25;
    int src = ei[e], dst = ei[E + e];
    float coef = g_dinv[src] * g_dinv[dst];
    float4 v = *(const float4*)(g_xw + src * HD + c * 4);
    float* op = o + dst * HD + c * 4;
    atomicAdd(op + 0, v.x * coef); atomicAdd(op + 1, v.y * coef);
    atomicAdd(op + 2, v.z * coef); atomicAdd(op + 3, v.w * coef);
}
__global__ void k_edge1(const int* __restrict__ ei, int E) { edge_body(g_xc1, ei, E); }
__global__ void k_edge2(const int* __restrict__ ei, int E) { edge_body(g_xc2, ei, E); }
__global__ void k_build_x(const int* __restrict__ idc, int N) {
    int gid = blockIdx.x * blockDim.x + threadIdx.x;
    if (gid >= N * 2 * HD) return;
    int n = gid / (2 * HD), j = gid - n * 2 * HD;
    float v = (j < HD) ? g_xc1[n * HD + j] : g_hn[idc[n] * HD + (j - HD)];
    g_x[gid] = fmaxf(v, 0.f);
}
__global__ void k_final(const int* __restrict__ idc, float* __restrict__ out, int N) {
    int gid = blockIdx.x * blockDim.x + threadIdx.x;
    if (gid >= N * 2 * HD) return;
    int n = gid / (2 * HD), j = gid - n * 2 * HD;
    out[gid] = (j < HD) ? fmaxf(g_xc2[n * HD + j], 0.f) : g_xc1[idc[n] * HD + (j - HD)];
}

extern "C" void kernel_launch(void* const* d_in, const int* in_sizes, int n_in,
                              void* d_out, int out_size)
{
    const int*   feat    = (const int*)  d_in[0];
    const int*   ei      = (const int*)  d_in[1];
    const int*   indices = (const int*)  d_in[2];
    const float* h0      = (const float*)d_in[3];
    const float* emb     = (const float*)d_in[4];
    const float* W_ih    = (const float*)d_in[5];
    const float* W_hh    = (const float*)d_in[6];
    const float* b_ih    = (const float*)d_in[7];
    const float* b_hh    = (const float*)d_in[8];
    const float* W1      = (const float*)d_in[9];
    const float* b1      = (const float*)d_in[10];
    const float* W2      = (const float*)d_in[11];
    const float* b2      = (const float*)d_in[12];
    float* out = (float*)d_out;

    const int N = in_sizes[0] / SEQL;
    const int E = in_sizes[1] / 2;
    const int V = in_sizes[4] / HD;
    const int gtiles = (N + 63) / 64;
    const int etiles = (V + 63) / 64;

    cudaFuncSetAttribute(k_gru_mma, cudaFuncAttributeMaxDynamicSharedMemorySize, MMASMEM);
    cudaFuncSetAttribute(k_embW,    cudaFuncAttributeMaxDynamicSharedMemorySize, EMBW_SMEM);
    cudaFuncSetAttribute(k_gemm1,   cudaFuncAttributeMaxDynamicSharedMemorySize, (100*64 + 100*100) * 4);
    cudaFuncSetAttribute(k_gemm2,   cudaFuncAttributeMaxDynamicSharedMemorySize, (200*64 + 200*100) * 4);

    k_deg_init <<<(N + 255) / 256, 256>>>(N);
    k_deg_edges<<<(E + 255) / 256, 256>>>(ei, E);
    k_embW<<<NSM, 320, EMBW_SMEM>>>(emb, W_ih, b_ih, V, etiles);
    k_gru_mma<<<NSM, 256, MMASMEM>>>(h0, feat, W_hh, b_hh, N, gtiles);   // ncu slot 3
    k_dinv<<<(N + 255) / 256, 256>>>(N);

    k_gemm1<<<(N + 63) / 64, 256, (100*64 + 100*100) * 4>>>(W1, N);
    k_init1<<<(N * HD + 255) / 256, 256>>>(b1, N);
    k_edge1<<<(E * 25 + 255) / 256, 256>>>(ei, E);
    k_build_x<<<(N * 2 * HD + 255) / 256, 256>>>(indices, N);
    k_gemm2<<<(N + 63) / 64, 256, (200*64 + 200*100) * 4>>>(W2, N);
    k_init2<<<(N * HD + 255) / 256, 256>>>(b2, N);
    k_edge2<<<(E * 25 + 255) / 256, 256>>>(ei, E);
    k_final<<<(N * 2 * HD + 255) / 256, 256>>>(indices, out, N);
}

// round 10
// speedup vs baseline: 1.4392x; 1.2180x over previous
#include <cuda_runtime.h>
#include <cuda_bf16.h>
#include <cstdint>

#define NMAX   60000
#define VMAX   50000
#define SEQL   30
#define HD     100
#define G3     300
#define NSM    152

typedef unsigned long long u64;

__device__ float g_embW[VMAX * G3];
__device__ float g_hn  [NMAX * HD];
__device__ float g_xw  [NMAX * HD];
__device__ float g_xc1 [NMAX * HD];
__device__ float g_xc2 [NMAX * HD];
__device__ float g_x   [NMAX * 2*HD];
__device__ float g_dinv[NMAX];
__device__ int   g_deg [NMAX];

__device__ __forceinline__ u64 pack2(float lo, float hi) {
    u64 r; asm("mov.b64 %0, {%1, %2};" : "=l"(r) : "f"(lo), "f"(hi)); return r;
}
__device__ __forceinline__ void unpack2(u64 v, float &lo, float &hi) {
    asm("mov.b64 {%0, %1}, %2;" : "=f"(lo), "=f"(hi) : "l"(v));
}
__device__ __forceinline__ u64 fma2(u64 a, u64 b, u64 c) {
    u64 d; asm("fma.rn.f32x2 %0, %1, %2, %3;" : "=l"(d) : "l"(a), "l"(b), "l"(c)); return d;
}
__device__ __forceinline__ float sigmf(float x) { return __fdividef(1.f, 1.f + __expf(-x)); }
__device__ __forceinline__ float tanh_f(float x) {
    return fmaf(2.f, __fdividef(1.f, 1.f + __expf(-2.f * x)), -1.f);
}
__device__ __forceinline__ float bf16f(uint32_t b16) {
    uint32_t u = b16 << 16; float f; asm("mov.b32 %0, %1;" : "=f"(f) : "r"(u)); return f;
}
__device__ __forceinline__ uint32_t s2u(const void* p) {
    uint32_t a; asm("{ .reg .u64 t; cvta.to.shared.u64 t, %1; cvt.u32.u64 %0, t; }" : "=r"(a) : "l"(p));
    return a;
}

// ================= degree =================
__global__ void k_deg_init(int N) {
    int i = blockIdx.x * blockDim.x + threadIdx.x; if (i < N) g_deg[i] = 1;
}
__global__ void k_deg_edges(const int* __restrict__ ei, int E) {
    int e = blockIdx.x * blockDim.x + threadIdx.x; if (e < E) atomicAdd(&g_deg[ei[E + e]], 1);
}
__global__ void k_dinv(int N) {
    int i = blockIdx.x * blockDim.x + threadIdx.x; if (i < N) g_dinv[i] = rsqrtf((float)g_deg[i]);
}

// ================= embW table (fp32, proven) =================
#define EMBW_SMEM ((30000 + 6400) * 4)
__global__ __launch_bounds__(320, 1)
void k_embW(const float* __restrict__ emb, const float* __restrict__ W_ih,
            const float* __restrict__ b_ih, int V, int ntiles)
{
    extern __shared__ float sm[];
    float* sW = sm; float* se = sm + 30000;
    const int tid = threadIdx.x, n = tid & 63, jc = tid >> 6;
    for (int idx = tid; idx < G3 * HD; idx += 320) {
        int c = idx / HD, k = idx - c * HD;
        sW[k * G3 + c] = W_ih[idx];
    }
    for (int tile = blockIdx.x; tile < ntiles; tile += gridDim.x) {
        const int base = tile * 64;
        __syncthreads();
        for (int idx = tid; idx < 64 * HD; idx += 320) {
            int nn = idx / HD, k = idx - nn * HD;
            se[k * 64 + nn] = emb[min(base + nn, V - 1) * HD + k];
        }
        __syncthreads();
        u64 acc[30];
        #pragma unroll
        for (int p = 0; p < 30; p++) acc[p] = 0ull;
        const float* wr0 = sW + jc * 60;
        #pragma unroll 2
        for (int k = 0; k < HD; k++) {
            float xv = se[k * 64 + n];
            u64 x2 = pack2(xv, xv);
            const float* wr = wr0 + k * G3;
            #pragma unroll
            for (int p = 0; p < 30; p++) acc[p] = fma2(*(const u64*)(wr + p * 2), x2, acc[p]);
        }
        int v = base + n;
        if (v < V) {
            float* o = g_embW + (long long)v * G3 + jc * 60;
            const float* bp = b_ih + jc * 60;
            #pragma unroll
            for (int p = 0; p < 30; p++) {
                float lo, hi; unpack2(acc[p], lo, hi);
                float2 w; w.x = lo + bp[p*2]; w.y = hi + bp[p*2+1];
                *(float2*)(o + p*2) = w;
            }
        }
    }
}

// ================= HMMA GRU (mma.sync m16n8k16 bf16, 512 thr) =================
// 16 warps: m = wid&3 (m-tile of 16 rows), nq = wid>>2 (q-quarter: 4/3/3/3 of
// the 13 q-cols per gate). Warp computes r/z/n of its q set -> thread-local
// gate math. C regs <= 3*4*4 = 48 -> no spills, 4 warps/SMSP.
#define FRAG_OFF 0
#define A_OFF    139776
#define A_STR    496
#define TOK_OFF  171520
#define BHH_OFF  179200
#define MMASMEM  180400

__global__ __launch_bounds__(512, 1)
void k_gru_mma(const float* __restrict__ h0, const int* __restrict__ feat,
               const float* __restrict__ W_hh, const float* __restrict__ b_hh,
               int n_nodes, int ntiles)
{
    extern __shared__ char smc[];
    const uint32_t sb = s2u(smc);
    const int tid = threadIdx.x, wid = tid >> 5, lane = tid & 31;
    const int m = wid & 3, nq = wid >> 2;
    const int g = lane >> 2, t = lane & 3;
    const int qlo  = (nq == 0) ? 0 : 1 + 3 * nq;      // 0,4,7,10
    const int qcnt = (nq == 0) ? 4 : 3;
    float* sbhh = (float*)(smc + BHH_OFF);
    int*   stok = (int*)(smc + TOK_OFF);

    // ---- one-time: B fragments + biases ----
    for (int w = tid; w < 14 * 39 * 32; w += 512) {
        int lan = w & 31, tile = w >> 5;
        int nt = tile % 39, ktd = tile / 39;
        int gg = lan >> 2, tt = lan & 3;
        int gate = nt / 13, j = (nt % 13) * 8 + gg;
        bool isLo = (ktd >= 7);
        int k0 = (isLo ? ktd - 7 : ktd) * 16 + tt * 2;
        uint32_t br[2];
        #pragma unroll
        for (int r = 0; r < 2; r++) {
            uint32_t pk = 0;
            #pragma unroll
            for (int e = 0; e < 2; e++) {
                int kk = k0 + r * 8 + e;
                uint16_t bits = 0;
                if (j < 100 && kk < 100) {
                    float wv = W_hh[(gate * 100 + j) * 100 + kk];
                    __nv_bfloat16 hb = __float2bfloat16_rn(wv);
                    if (isLo) hb = __float2bfloat16_rn(wv - __bfloat162float(hb));
                    bits = __bfloat16_as_ushort(hb);
                }
                pk |= (uint32_t)bits << (16 * e);
            }
            br[r] = pk;
        }
        *(uint2*)(smc + FRAG_OFF + tile * 256 + lan * 8) = make_uint2(br[0], br[1]);
    }
    for (int i = tid; i < G3; i += 512) sbhh[i] = b_hh[i];
    __syncthreads();

    const int n0l = m * 16 + g, n1l = n0l + 8;

    for (int tile = blockIdx.x; tile < ntiles; tile += gridDim.x) {
        const int nbase = tile * 64;
        __syncthreads();
        for (int i = tid; i < 64 * SEQL; i += 512) {
            int nl = i / SEQL, tt = i - nl * SEQL;
            stok[nl * SEQL + tt] = feat[(long long)min(nbase + nl, n_nodes - 1) * SEQL + tt];
        }
        for (int i = tid; i < 64 * 248; i += 512) {
            int row = i / 248, col = i - row * 248;
            uint16_t v = 0;
            if (col < 224) {
                int seg = col / 112, k = col - seg * 112;
                if (k < 100) {
                    float hv = h0[(long long)min(nbase + row, n_nodes - 1) * HD + k];
                    __nv_bfloat16 hb = __float2bfloat16_rn(hv);
                    if (seg == 1) hb = __float2bfloat16_rn(hv - __bfloat162float(hb));
                    v = __bfloat16_as_ushort(hb);
                }
            }
            *(uint16_t*)(smc + A_OFF + row * A_STR + col * 2) = v;
        }
        __syncthreads();

        for (int st = 0; st < SEQL; st++) {
            // ---- GEMM: gh = [h_hi|h_lo|h_hi] x [W_hi|W_hi|W_lo] ----
            float C[3][4][4];
            #pragma unroll
            for (int ga = 0; ga < 3; ga++)
                #pragma unroll
                for (int qi = 0; qi < 4; qi++)
                    #pragma unroll
                    for (int e = 0; e < 4; e++) C[ga][qi][e] = 0.f;

            const uint32_t abase = sb + A_OFF + (m * 16 + (lane & 15)) * A_STR + (lane >> 4) * 16;
            #pragma unroll
            for (int kt = 0; kt < 21; kt++) {
                int acol = (kt < 7) ? kt * 32 : (kt < 14) ? 224 + (kt - 7) * 32 : (kt - 14) * 32;
                int ktd  = (kt < 7) ? kt : kt - 7;
                uint32_t a0, a1, a2, a3;
                asm volatile("ldmatrix.sync.aligned.m8n8.x4.shared.b16 {%0,%1,%2,%3}, [%4];"
                    : "=r"(a0), "=r"(a1), "=r"(a2), "=r"(a3) : "r"(abase + acol));
                #pragma unroll
                for (int ga = 0; ga < 3; ga++) {
                    #pragma unroll
                    for (int qi = 0; qi < 4; qi++) {
                        if (qi < qcnt) {
                            int nt = ga * 13 + qlo + qi;
                            uint32_t b0, b1;
                            asm volatile("ld.shared.v2.b32 {%0,%1}, [%2];"
                                : "=r"(b0), "=r"(b1)
                                : "r"(sb + FRAG_OFF + (ktd * 39 + nt) * 256 + lane * 8));
                            asm volatile(
                                "mma.sync.aligned.m16n8k16.row.col.f32.bf16.bf16.f32 "
                                "{%0,%1,%2,%3}, {%4,%5,%6,%7}, {%8,%9}, {%0,%1,%2,%3};"
                                : "+f"(C[ga][qi][0]), "+f"(C[ga][qi][1]),
                                  "+f"(C[ga][qi][2]), "+f"(C[ga][qi][3])
                                : "r"(a0), "r"(a1), "r"(a2), "r"(a3), "r"(b0), "r"(b1));
                        }
                    }
                }
            }
            __syncthreads();   // all A reads done before h writes

            // ---- gate phase ----
            const bool last = (st == SEQL - 1);
            #pragma unroll
            for (int qi = 0; qi < 4; qi++) {
                if (qi < qcnt) {
                    int j = (qlo + qi) * 8 + 2 * t;
                    if (j < 100) {
                        float2 bhr = *(const float2*)(sbhh + j);
                        float2 bhz = *(const float2*)(sbhh + 100 + j);
                        float2 bhn = *(const float2*)(sbhh + 200 + j);
                        #pragma unroll
                        for (int nd = 0; nd < 2; nd++) {
                            int nl = nd ? n1l : n0l;
                            int gn = nbase + nl;
                            int tok = stok[nl * SEQL + st];
                            const float* ew = g_embW + (long long)tok * G3;
                            float2 xr = __ldg((const float2*)(ew + j));
                            float2 xz = __ldg((const float2*)(ew + 100 + j));
                            float2 xn = __ldg((const float2*)(ew + 200 + j));
                            char* hrow = smc + A_OFF + nl * A_STR;
                            uint32_t hhi = *(uint32_t*)(hrow + 2 * j);
                            uint32_t hlo = *(uint32_t*)(hrow + 224 + 2 * j);
                            float ho0 = bf16f(hhi & 0xffffu) + bf16f(hlo & 0xffffu);
                            float ho1 = bf16f(hhi >> 16) + bf16f(hlo >> 16);
                            float r0 = sigmf(xr.x + C[0][qi][2*nd]   + bhr.x);
                            float r1 = sigmf(xr.y + C[0][qi][2*nd+1] + bhr.y);
                            float z0 = sigmf(xz.x + C[1][qi][2*nd]   + bhz.x);
                            float z1 = sigmf(xz.y + C[1][qi][2*nd+1] + bhz.y);
                            float nv0 = tanh_f(xn.x + r0 * (C[2][qi][2*nd]   + bhn.x));
                            float nv1 = tanh_f(xn.y + r1 * (C[2][qi][2*nd+1] + bhn.y));
                            float h0n = nv0 + z0 * (ho0 - nv0);
                            float h1n = nv1 + z1 * (ho1 - nv1);
                            if (last) {
                                if (gn < n_nodes)
                                    *(float2*)(g_hn + (long long)gn * HD + j) = make_float2(h0n, h1n);
                            } else {
                                __nv_bfloat16 ah = __float2bfloat16_rn(h0n);
                                __nv_bfloat16 bh = __float2bfloat16_rn(h1n);
                                __nv_bfloat16 al = __float2bfloat16_rn(h0n - __bfloat162float(ah));
                                __nv_bfloat16 bl = __float2bfloat16_rn(h1n - __bfloat162float(bh));
                                *(uint32_t*)(hrow + 2 * j) =
                                    (uint32_t)__bfloat16_as_ushort(ah) |
                                    ((uint32_t)__bfloat16_as_ushort(bh) << 16);
                                *(uint32_t*)(hrow + 224 + 2 * j) =
                                    (uint32_t)__bfloat16_as_ushort(al) |
                                    ((uint32_t)__bfloat16_as_ushort(bl) << 16);
                            }
                        }
                    }
                }
            }
            __syncthreads();   // h writes visible before next step's GEMM
        }
    }
}

// ================= small GEMMs / GCN / glue (proven) =================
template<int K>
__device__ __forceinline__ void gemm_body(const float* __restrict__ x,
    const float* __restrict__ W, float* __restrict__ outp, int N)
{
    extern __shared__ float sg[];
    float* sxT = sg; float* sW = sg + K * 64;
    const int tid = threadIdx.x, base = blockIdx.x * 64;
    for (int idx = tid; idx < K * 64; idx += 256) {
        int nn = idx / K, k = idx - nn * K;
        sxT[k * 64 + nn] = x[min(base + nn, N - 1) * K + k];
    }
    for (int idx = tid; idx < K * 100; idx += 256) sW[idx] = W[idx];
    __syncthreads();
    const int n = tid & 63, q = tid >> 6;
    float acc[25];
    #pragma unroll
    for (int j = 0; j < 25; j++) acc[j] = 0.f;
    #pragma unroll 4
    for (int k = 0; k < K; k++) {
        float xk = sxT[k * 64 + n];
        const float* wr = sW + k * 100 + q * 25;
        #pragma unroll
        for (int j = 0; j < 25; j++) acc[j] = fmaf(xk, wr[j], acc[j]);
    }
    int ng = base + n;
    if (ng < N) {
        float* o = outp + ng * 100 + q * 25;
        #pragma unroll
        for (int j = 0; j < 25; j++) o[j] = acc[j];
    }
}
__global__ __launch_bounds__(256) void k_gemm1(const float* __restrict__ W1, int N) {
    gemm_body<100>(g_hn, W1, g_xw, N);
}
__global__ __launch_bounds__(256) void k_gemm2(const float* __restrict__ W2, int N) {
    gemm_body<200>(g_x, W2, g_xw, N);
}
__device__ __forceinline__ void init_self(const float* __restrict__ b, float* __restrict__ o, int N) {
    int gid = blockIdx.x * blockDim.x + threadIdx.x;
    if (gid >= N * HD) return;
    int n = gid / HD, j = gid - n * HD;
    float di = g_dinv[n];
    o[gid] = fmaf(g_xw[gid], di * di, b[j]);
}
__global__ void k_init1(const float* __restrict__ b1, int N) { init_self(b1, g_xc1, N); }
__global__ void k_init2(const float* __restrict__ b2, int N) { init_self(b2, g_xc2, N); }
__device__ __forceinline__ void edge_body(float* __restrict__ o, const int* __restrict__ ei, int E) {
    int gid = blockIdx.x * blockDim.x + threadIdx.x;
    if (gid >= E * 25) return;
    int e = gid / 25, c = gid - e * 25;
    int src = ei[e], dst = ei[E + e];
    float coef = g_dinv[src] * g_dinv[dst];
    float4 v = *(const float4*)(g_xw + src * HD + c * 4);
    float* op = o + dst * HD + c * 4;
    atomicAdd(op + 0, v.x * coef); atomicAdd(op + 1, v.y * coef);
    atomicAdd(op + 2, v.z * coef); atomicAdd(op + 3, v.w * coef);
}
__global__ void k_edge1(const int* __restrict__ ei, int E) { edge_body(g_xc1, ei, E); }
__global__ void k_edge2(const int* __restrict__ ei, int E) { edge_body(g_xc2, ei, E); }
__global__ void k_build_x(const int* __restrict__ idc, int N) {
    int gid = blockIdx.x * blockDim.x + threadIdx.x;
    if (gid >= N * 2 * HD) return;
    int n = gid / (2 * HD), j = gid - n * 2 * HD;
    float v = (j < HD) ? g_xc1[n * HD + j] : g_hn[idc[n] * HD + (j - HD)];
    g_x[gid] = fmaxf(v, 0.f);
}
__global__ void k_final(const int* __restrict__ idc, float* __restrict__ out, int N) {
    int gid = blockIdx.x * blockDim.x + threadIdx.x;
    if (gid >= N * 2 * HD) return;
    int n = gid / (2 * HD), j = gid - n * 2 * HD;
    out[gid] = (j < HD) ? fmaxf(g_xc2[n * HD + j], 0.f) : g_xc1[idc[n] * HD + (j - HD)];
}

extern "C" void kernel_launch(void* const* d_in, const int* in_sizes, int n_in,
                              void* d_out, int out_size)
{
    const int*   feat    = (const int*)  d_in[0];
    const int*   ei      = (const int*)  d_in[1];
    const int*   indices = (const int*)  d_in[2];
    const float* h0      = (const float*)d_in[3];
    const float* emb     = (const float*)d_in[4];
    const float* W_ih    = (const float*)d_in[5];
    const float* W_hh    = (const float*)d_in[6];
    const float* b_ih    = (const float*)d_in[7];
    const float* b_hh    = (const float*)d_in[8];
    const float* W1      = (const float*)d_in[9];
    const float* b1      = (const float*)d_in[10];
    const float* W2      = (const float*)d_in[11];
    const float* b2      = (const float*)d_in[12];
    float* out = (float*)d_out;

    const int N = in_sizes[0] / SEQL;
    const int E = in_sizes[1] / 2;
    const int V = in_sizes[4] / HD;
    const int gtiles = (N + 63) / 64;
    const int etiles = (V + 63) / 64;

    cudaFuncSetAttribute(k_gru_mma, cudaFuncAttributeMaxDynamicSharedMemorySize, MMASMEM);
    cudaFuncSetAttribute(k_embW,    cudaFuncAttributeMaxDynamicSharedMemorySize, EMBW_SMEM);
    cudaFuncSetAttribute(k_gemm1,   cudaFuncAttributeMaxDynamicSharedMemorySize, (100*64 + 100*100) * 4);
    cudaFuncSetAttribute(k_gemm2,   cudaFuncAttributeMaxDynamicSharedMemorySize, (200*64 + 200*100) * 4);

    k_deg_init <<<(N + 255) / 256, 256>>>(N);
    k_deg_edges<<<(E + 255) / 256, 256>>>(ei, E);
    k_embW<<<NSM, 320, EMBW_SMEM>>>(emb, W_ih, b_ih, V, etiles);
    k_gru_mma<<<NSM, 512, MMASMEM>>>(h0, feat, W_hh, b_hh, N, gtiles);   // ncu slot 3
    k_dinv<<<(N + 255) / 256, 256>>>(N);

    k_gemm1<<<(N + 63) / 64, 256, (100*64 + 100*100) * 4>>>(W1, N);
    k_init1<<<(N * HD + 255) / 256, 256>>>(b1, N);
    k_edge1<<<(E * 25 + 255) / 256, 256>>>(ei, E);
    k_build_x<<<(N * 2 * HD + 255) / 256, 256>>>(indices, N);
    k_gemm2<<<(N + 63) / 64, 256, (200*64 + 200*100) * 4>>>(W2, N);
    k_init2<<<(N * HD + 255) / 256, 256>>>(b2, N);
    k_edge2<<<(E * 25 + 255) / 256, 256>>>(ei, E);
    k_final<<<(N * 2 * HD + 255) / 256, 256>>>(indices, out, N);
}